// round 8
// baseline (speedup 1.0000x reference)
#include <cuda_runtime.h>

#define EPSV   1e-5f
#define DW_THR 4.0f
#define PW_THR 0.001f

// Shapes: B=64, C=128, O=256, H=W=56, HW=3136
__device__ float g_y[64 * 128 * 3136];   // pruned depthwise output [B,C,HW]
__device__ int   g_keep[64 * 128];       // per-(b,c) keep flag
__device__ int   g_idx[64 * 128];        // per-b compacted kept-channel list
__device__ int   g_cnt[64];              // per-b kept count
__device__ int   g_max[64 * 256];        // per-(b,o) max(z) as int bits (z>=0)
__device__ int   g_done[64 * 2];         // per-(b,o-tile) completion counters

// ---------------------------------------------------------------------------
// packed fp32x2 helpers (Blackwell FFMA2)
// ---------------------------------------------------------------------------
__device__ __forceinline__ unsigned long long fma2(unsigned long long a,
                                                   unsigned long long b,
                                                   unsigned long long c) {
    unsigned long long d;
    asm("fma.rn.f32x2 %0, %1, %2, %3;" : "=l"(d) : "l"(a), "l"(b), "l"(c));
    return d;
}
__device__ __forceinline__ unsigned long long mul2(unsigned long long a,
                                                   unsigned long long b) {
    unsigned long long d;
    asm("mul.rn.f32x2 %0, %1, %2;" : "=l"(d) : "l"(a), "l"(b));
    return d;
}
__device__ __forceinline__ unsigned long long pk2(float lo, float hi) {
    unsigned long long d;
    asm("mov.b64 %0, {%1, %2};" : "=l"(d) : "f"(lo), "f"(hi));
    return d;
}
__device__ __forceinline__ float2 upk2(unsigned long long v) {
    float2 r;
    asm("mov.b64 {%0, %1}, %2;" : "=f"(r.x), "=f"(r.y) : "l"(v));
    return r;
}

// ---------------------------------------------------------------------------
// Depthwise 3x3 + bias + BN1 + ReLU + per-(b,c) prune.
// FFMA2 column pairs: 224 threads = 28 col-pairs x 8 bands x 7 rows.
// Per-lane fp32x2 ops are bit-identical to the scalar FMA chain.
// ---------------------------------------------------------------------------
__global__ __launch_bounds__(256) void dw_kernel(
    const float* __restrict__ x,
    const float* __restrict__ dw_w, const float* __restrict__ dw_b,
    const float* __restrict__ g1,  const float* __restrict__ b1,
    const float* __restrict__ m1,  const float* __restrict__ v1)
{
    __shared__ float sx[3136];
    __shared__ float red[8];
    __shared__ float s_bmax;

    const int slice = blockIdx.x;          // b*128 + c
    const int c = slice & 127;
    const float* xs = x + (size_t)slice * 3136;

    const unsigned long long ww0 = pk2(dw_w[c*9+0], dw_w[c*9+0]);
    const unsigned long long ww1 = pk2(dw_w[c*9+1], dw_w[c*9+1]);
    const unsigned long long ww2 = pk2(dw_w[c*9+2], dw_w[c*9+2]);
    const unsigned long long ww3 = pk2(dw_w[c*9+3], dw_w[c*9+3]);
    const unsigned long long ww4 = pk2(dw_w[c*9+4], dw_w[c*9+4]);
    const unsigned long long ww5 = pk2(dw_w[c*9+5], dw_w[c*9+5]);
    const unsigned long long ww6 = pk2(dw_w[c*9+6], dw_w[c*9+6]);
    const unsigned long long ww7 = pk2(dw_w[c*9+7], dw_w[c*9+7]);
    const unsigned long long ww8 = pk2(dw_w[c*9+8], dw_w[c*9+8]);
    const float s = g1[c] * rsqrtf(v1[c] + EPSV);
    const float t = fmaf(dw_b[c] - m1[c], s, b1[c]);
    const unsigned long long ss = pk2(s, s);
    const unsigned long long tt = pk2(t, t);

    const int tid = threadIdx.x;

    {   // stage slice: 784 coalesced float4
        const float4* x4 = (const float4*)xs;
        float4* s4 = (float4*)sx;
        for (int i = tid; i < 784; i += 256) s4[i] = x4[i];
    }
    __syncthreads();

    float2 lv[7];
    float mx = 0.f;
    int p = 0, band = 0;
    if (tid < 224) {
        band = tid / 28;               // 0..7
        p    = tid - band * 28;        // col pair 0..27 -> cols 2p, 2p+1
        const bool cL = (p > 0), cR = (p < 27);
        const int col = 2 * p;
        const int r0  = band * 7;      // first output row

        unsigned long long r0q0, r0q1, r0q2, r1q0, r1q1, r1q2;
        {
            float c0 = 0.f, c1 = 0.f, c2 = 0.f, c3 = 0.f;
            if (r0 > 0) {
                int a = (r0 - 1) * 56 + col;
                c0 = cL ? sx[a - 1] : 0.f;
                c1 = sx[a]; c2 = sx[a + 1];
                c3 = cR ? sx[a + 2] : 0.f;
            }
            r0q0 = pk2(c0, c1); r0q1 = pk2(c1, c2); r0q2 = pk2(c2, c3);
        }
        {
            int a = r0 * 56 + col;
            float c0 = cL ? sx[a - 1] : 0.f;
            float c1 = sx[a], c2 = sx[a + 1];
            float c3 = cR ? sx[a + 2] : 0.f;
            r1q0 = pk2(c0, c1); r1q1 = pk2(c1, c2); r1q2 = pk2(c2, c3);
        }

#pragma unroll
        for (int j = 0; j < 7; j++) {
            const int rr = r0 + j + 1;
            unsigned long long r2q0, r2q1, r2q2;
            {
                float c0 = 0.f, c1 = 0.f, c2 = 0.f, c3 = 0.f;
                if (rr < 56) {
                    int a = rr * 56 + col;
                    c0 = cL ? sx[a - 1] : 0.f;
                    c1 = sx[a]; c2 = sx[a + 1];
                    c3 = cR ? sx[a + 2] : 0.f;
                }
                r2q0 = pk2(c0, c1); r2q1 = pk2(c1, c2); r2q2 = pk2(c2, c3);
            }
            unsigned long long acc = mul2(r0q0, ww0);
            acc = fma2(r0q1, ww1, acc); acc = fma2(r0q2, ww2, acc);
            acc = fma2(r1q0, ww3, acc); acc = fma2(r1q1, ww4, acc);
            acc = fma2(r1q2, ww5, acc);
            acc = fma2(r2q0, ww6, acc); acc = fma2(r2q1, ww7, acc);
            acc = fma2(r2q2, ww8, acc);
            acc = fma2(acc, ss, tt);
            float2 pr = upk2(acc);
            float z0 = fmaxf(pr.x, 0.f), z1 = fmaxf(pr.y, 0.f);
            lv[j] = make_float2(z0, z1);
            mx = fmaxf(mx, fmaxf(z0, z1));
            r0q0 = r1q0; r0q1 = r1q1; r0q2 = r1q2;
            r1q0 = r2q0; r1q1 = r2q1; r1q2 = r2q2;
        }
    }

    for (int off = 16; off; off >>= 1)
        mx = fmaxf(mx, __shfl_xor_sync(0xffffffffu, mx, off));
    if ((tid & 31) == 0) red[tid >> 5] = mx;
    __syncthreads();
    if (tid == 0) {
        float m = red[0];
#pragma unroll
        for (int i = 1; i < 8; i++) m = fmaxf(m, red[i]);
        s_bmax = m;
        g_keep[slice] = (m >= DW_THR) ? 1 : 0;
    }
    __syncthreads();

    if (s_bmax >= DW_THR && tid < 224) {
        float* yo = g_y + (size_t)slice * 3136 + band * 7 * 56 + 2 * p;
#pragma unroll
        for (int j = 0; j < 7; j++)
            *(float2*)(yo + j * 56) = lv[j];
    }
}

// ---------------------------------------------------------------------------
// Per-batch compaction + zero g_max and g_done (graph-replay safe)
// ---------------------------------------------------------------------------
__global__ void compact_kernel() {
    const int b = blockIdx.x;
    const int tid = threadIdx.x;              // 256 threads
    g_max[b * 256 + tid] = 0;
    if (tid < 2) g_done[b * 2 + tid] = 0;
    __shared__ int wcnt[4];
    if (tid < 128) {
        const int f = g_keep[b * 128 + tid];
        const unsigned bal = __ballot_sync(0xffffffffu, f);
        const int lane = tid & 31, w = tid >> 5;
        const int pre = __popc(bal & ((1u << lane) - 1u));
        if (lane == 0) wcnt[w] = __popc(bal);
        __syncthreads();
        int off = 0;
#pragma unroll
        for (int i = 0; i < 4; i++) if (i < w) off += wcnt[i];
        if (f) g_idx[b * 128 + off + pre] = tid;
        if (tid == 0) g_cnt[b] = wcnt[0] + wcnt[1] + wcnt[2] + wcnt[3];
    } else {
        __syncthreads();
    }
}

// ---------------------------------------------------------------------------
// Pointwise GEMM over compacted K + BN2 + ReLU + per-(b,o) max
// + FUSED last-block prune (no separate prune launch).
// Tile 128(O) x 64(HW), 8x4 microtile, FFMA2, KT=8.
// grid = (49, 2, 64), 256 threads.
// ---------------------------------------------------------------------------
#define KT 8
__global__ __launch_bounds__(256, 4) void pw_kernel(
    const float* __restrict__ pw_w, const float* __restrict__ pw_b,
    const float* __restrict__ g2,  const float* __restrict__ b2,
    const float* __restrict__ m2,  const float* __restrict__ v2,
    float* __restrict__ out)
{
    __shared__ float sW[KT][132];   // [k][o]
    __shared__ float sY[KT][68];    // [k][hw]
    __shared__ int   sidx[KT];

    const int tid = threadIdx.x;
    const int tx = tid & 15;        // hw: 16 threads x 4
    const int ty = tid >> 4;        // o : 16 threads x 8
    const int hwb = blockIdx.x * 64;
    const int ob  = blockIdx.y * 128;
    const int b   = blockIdx.z;

    const int cnt = g_cnt[b];
    const int ntiles = (cnt + KT - 1) / KT;

    unsigned long long acc[4][4];
#pragma unroll
    for (int pp = 0; pp < 4; pp++)
#pragma unroll
        for (int q = 0; q < 4; q++) acc[pp][q] = 0ull;

    for (int kt = 0; kt < ntiles; kt++) {
        int klim = cnt - kt * KT;
        if (klim > KT) klim = KT;
        const int kstage = (klim + 3) & ~3;

        if (tid < KT) {
            int kk = kt * KT + tid;
            sidx[tid] = (kk < cnt) ? g_idx[b * 128 + kk] : -1;
        }
        __syncthreads();

#pragma unroll
        for (int j = 0; j < 4; j++) {
            int idx = j * 256 + tid;        // 1024 = 8k x 128o
            int o = idx >> 3, k = idx & 7;
            if (k < kstage) {
                int ch = sidx[k];
                sW[k][o] = (ch >= 0) ? pw_w[(ob + o) * 128 + ch] : 0.f;
            }
        }
        if (tid < 128) {
            int k = tid >> 4, f4 = tid & 15;
            if (k < kstage) {
                int ch = sidx[k];
                float4 v = make_float4(0.f, 0.f, 0.f, 0.f);
                if (ch >= 0)
                    v = *(const float4*)(g_y + ((size_t)(b * 128 + ch)) * 3136 + hwb + f4 * 4);
                *(float4*)&sY[k][f4 * 4] = v;
            }
        }
        __syncthreads();

        for (int k0 = 0; k0 < klim; k0 += 4) {
#pragma unroll
            for (int ku = 0; ku < 4; ku++) {
                int k = k0 + ku;
                float4 A0 = *(const float4*)&sW[k][ty * 8];
                float4 A1 = *(const float4*)&sW[k][ty * 8 + 4];
                float4 B0 = *(const float4*)&sY[k][tx * 4];
                unsigned long long av[4];
                av[0] = pk2(A0.x, A0.y); av[1] = pk2(A0.z, A0.w);
                av[2] = pk2(A1.x, A1.y); av[3] = pk2(A1.z, A1.w);
                unsigned long long bq[4];
                bq[0] = pk2(B0.x, B0.x); bq[1] = pk2(B0.y, B0.y);
                bq[2] = pk2(B0.z, B0.z); bq[3] = pk2(B0.w, B0.w);
#pragma unroll
                for (int pp = 0; pp < 4; pp++)
#pragma unroll
                    for (int q = 0; q < 4; q++)
                        acc[pp][q] = fma2(av[pp], bq[q], acc[pp][q]);
            }
        }
        __syncthreads();
    }

    // epilogue: BN2 + ReLU + per-(b,o) max + store
#pragma unroll
    for (int r = 0; r < 8; r++) {
        int o = ob + ty * 8 + r;
        float sc = g2[o] * rsqrtf(v2[o] + EPSV);
        float tt = fmaf(pw_b[o] - m2[o], sc, b2[o]);
        float z[4];
        float m = 0.f;
#pragma unroll
        for (int q = 0; q < 4; q++) {
            float2 pr = upk2(acc[r >> 1][q]);
            float v = (r & 1) ? pr.y : pr.x;
            float zz = fmaxf(fmaf(v, sc, tt), 0.f);
            z[q] = zz;
            m = fmaxf(m, zz);
        }
#pragma unroll
        for (int off = 1; off < 16; off <<= 1)
            m = fmaxf(m, __shfl_xor_sync(0xffffffffu, m, off));
        if (tx == 0) atomicMax(&g_max[b * 256 + o], __float_as_int(m));
        float* po = out + ((size_t)(b * 256 + o)) * 3136 + hwb + tx * 4;
        *(float4*)po = make_float4(z[0], z[1], z[2], z[3]);
    }

    // ---- fused prune: last block of this (b, o-tile) zeroes failing rows ----
    __threadfence();
    __shared__ int s_ticket;
    if (tid == 0) s_ticket = atomicAdd(&g_done[b * 2 + blockIdx.y], 1);
    __syncthreads();
    if (s_ticket == 48) {
        __shared__ unsigned failbits[4];
        if (tid < 128) {
            // idempotent atomic read: L2-coherent view of g_max (values >= 0)
            int mv = atomicMax(&g_max[b * 256 + ob + tid], 0);
            unsigned bal = __ballot_sync(0xffffffffu,
                                         __int_as_float(mv) < PW_THR);
            if ((tid & 31) == 0) failbits[tid >> 5] = bal;
        }
        __syncthreads();
        const float4 zz = make_float4(0.f, 0.f, 0.f, 0.f);
#pragma unroll
        for (int w = 0; w < 4; w++) {
            unsigned bits = failbits[w];
            while (bits) {
                int o = w * 32 + __ffs(bits) - 1;
                bits &= bits - 1;
                float4* p4 = (float4*)(out + ((size_t)(b * 256 + ob + o)) * 3136);
                for (int i = tid; i < 784; i += 256) p4[i] = zz;
            }
        }
    }
}

// ---------------------------------------------------------------------------
extern "C" void kernel_launch(void* const* d_in, const int* in_sizes, int n_in,
                              void* d_out, int out_size)
{
    const float* x    = (const float*)d_in[0];
    const float* dw_w = (const float*)d_in[1];
    const float* dw_b = (const float*)d_in[2];
    const float* g1   = (const float*)d_in[3];
    const float* b1   = (const float*)d_in[4];
    const float* m1   = (const float*)d_in[5];
    const float* v1   = (const float*)d_in[6];
    const float* pw_w = (const float*)d_in[7];
    const float* pw_b = (const float*)d_in[8];
    const float* g2   = (const float*)d_in[9];
    const float* b2   = (const float*)d_in[10];
    const float* m2   = (const float*)d_in[11];
    const float* v2   = (const float*)d_in[12];
    float* out = (float*)d_out;

    dw_kernel<<<64 * 128, 256>>>(x, dw_w, dw_b, g1, b1, m1, v1);
    compact_kernel<<<64, 256>>>();
    pw_kernel<<<dim3(49, 2, 64), 256>>>(pw_w, pw_b, g2, b2, m2, v2, out);
}

// round 10
// speedup vs baseline: 1.2210x; 1.2210x over previous
#include <cuda_runtime.h>

#define EPSV   1e-5f
#define DW_THR 4.0f
#define PW_THR 0.001f

// Shapes: B=64, C=128, O=256, H=W=56, HW=3136
__device__ float g_y[64 * 128 * 3136];   // pruned depthwise output [B,C,HW]
__device__ int   g_keep[64 * 128];       // per-(b,c) keep flag
__device__ int   g_idx[64 * 128];        // per-b compacted kept-channel list
__device__ int   g_cnt[64];              // per-b kept count

// ---------------------------------------------------------------------------
// packed fp32x2 helpers (Blackwell FFMA2)
// ---------------------------------------------------------------------------
__device__ __forceinline__ unsigned long long fma2(unsigned long long a,
                                                   unsigned long long b,
                                                   unsigned long long c) {
    unsigned long long d;
    asm("fma.rn.f32x2 %0, %1, %2, %3;" : "=l"(d) : "l"(a), "l"(b), "l"(c));
    return d;
}
__device__ __forceinline__ unsigned long long mul2(unsigned long long a,
                                                   unsigned long long b) {
    unsigned long long d;
    asm("mul.rn.f32x2 %0, %1, %2;" : "=l"(d) : "l"(a), "l"(b));
    return d;
}
__device__ __forceinline__ unsigned long long pk2(float lo, float hi) {
    unsigned long long d;
    asm("mov.b64 %0, {%1, %2};" : "=l"(d) : "f"(lo), "f"(hi));
    return d;
}
__device__ __forceinline__ float2 upk2(unsigned long long v) {
    float2 r;
    asm("mov.b64 {%0, %1}, %2;" : "=f"(r.x), "=f"(r.y) : "l"(v));
    return r;
}

// ---------------------------------------------------------------------------
// Depthwise 3x3 + bias + BN1 + ReLU + per-(b,c) prune. (round-7/8, passing)
// ---------------------------------------------------------------------------
__global__ __launch_bounds__(256) void dw_kernel(
    const float* __restrict__ x,
    const float* __restrict__ dw_w, const float* __restrict__ dw_b,
    const float* __restrict__ g1,  const float* __restrict__ b1,
    const float* __restrict__ m1,  const float* __restrict__ v1)
{
    __shared__ float sx[3136];
    __shared__ float red[8];
    __shared__ float s_bmax;

    const int slice = blockIdx.x;          // b*128 + c
    const int c = slice & 127;
    const float* xs = x + (size_t)slice * 3136;

    const unsigned long long ww0 = pk2(dw_w[c*9+0], dw_w[c*9+0]);
    const unsigned long long ww1 = pk2(dw_w[c*9+1], dw_w[c*9+1]);
    const unsigned long long ww2 = pk2(dw_w[c*9+2], dw_w[c*9+2]);
    const unsigned long long ww3 = pk2(dw_w[c*9+3], dw_w[c*9+3]);
    const unsigned long long ww4 = pk2(dw_w[c*9+4], dw_w[c*9+4]);
    const unsigned long long ww5 = pk2(dw_w[c*9+5], dw_w[c*9+5]);
    const unsigned long long ww6 = pk2(dw_w[c*9+6], dw_w[c*9+6]);
    const unsigned long long ww7 = pk2(dw_w[c*9+7], dw_w[c*9+7]);
    const unsigned long long ww8 = pk2(dw_w[c*9+8], dw_w[c*9+8]);
    const float s = g1[c] * rsqrtf(v1[c] + EPSV);
    const float t = fmaf(dw_b[c] - m1[c], s, b1[c]);
    const unsigned long long ss = pk2(s, s);
    const unsigned long long tt = pk2(t, t);

    const int tid = threadIdx.x;

    {   // stage slice: 784 coalesced float4
        const float4* x4 = (const float4*)xs;
        float4* s4 = (float4*)sx;
        for (int i = tid; i < 784; i += 256) s4[i] = x4[i];
    }
    __syncthreads();

    float2 lv[7];
    float mx = 0.f;
    int p = 0, band = 0;
    if (tid < 224) {
        band = tid / 28;               // 0..7
        p    = tid - band * 28;        // col pair -> cols 2p, 2p+1
        const bool cL = (p > 0), cR = (p < 27);
        const int col = 2 * p;
        const int r0  = band * 7;

        unsigned long long r0q0, r0q1, r0q2, r1q0, r1q1, r1q2;
        {
            float c0 = 0.f, c1 = 0.f, c2 = 0.f, c3 = 0.f;
            if (r0 > 0) {
                int a = (r0 - 1) * 56 + col;
                c0 = cL ? sx[a - 1] : 0.f;
                c1 = sx[a]; c2 = sx[a + 1];
                c3 = cR ? sx[a + 2] : 0.f;
            }
            r0q0 = pk2(c0, c1); r0q1 = pk2(c1, c2); r0q2 = pk2(c2, c3);
        }
        {
            int a = r0 * 56 + col;
            float c0 = cL ? sx[a - 1] : 0.f;
            float c1 = sx[a], c2 = sx[a + 1];
            float c3 = cR ? sx[a + 2] : 0.f;
            r1q0 = pk2(c0, c1); r1q1 = pk2(c1, c2); r1q2 = pk2(c2, c3);
        }

#pragma unroll
        for (int j = 0; j < 7; j++) {
            const int rr = r0 + j + 1;
            unsigned long long r2q0, r2q1, r2q2;
            {
                float c0 = 0.f, c1 = 0.f, c2 = 0.f, c3 = 0.f;
                if (rr < 56) {
                    int a = rr * 56 + col;
                    c0 = cL ? sx[a - 1] : 0.f;
                    c1 = sx[a]; c2 = sx[a + 1];
                    c3 = cR ? sx[a + 2] : 0.f;
                }
                r2q0 = pk2(c0, c1); r2q1 = pk2(c1, c2); r2q2 = pk2(c2, c3);
            }
            unsigned long long acc = mul2(r0q0, ww0);
            acc = fma2(r0q1, ww1, acc); acc = fma2(r0q2, ww2, acc);
            acc = fma2(r1q0, ww3, acc); acc = fma2(r1q1, ww4, acc);
            acc = fma2(r1q2, ww5, acc);
            acc = fma2(r2q0, ww6, acc); acc = fma2(r2q1, ww7, acc);
            acc = fma2(r2q2, ww8, acc);
            acc = fma2(acc, ss, tt);
            float2 pr = upk2(acc);
            float z0 = fmaxf(pr.x, 0.f), z1 = fmaxf(pr.y, 0.f);
            lv[j] = make_float2(z0, z1);
            mx = fmaxf(mx, fmaxf(z0, z1));
            r0q0 = r1q0; r0q1 = r1q1; r0q2 = r1q2;
            r1q0 = r2q0; r1q1 = r2q1; r1q2 = r2q2;
        }
    }

    for (int off = 16; off; off >>= 1)
        mx = fmaxf(mx, __shfl_xor_sync(0xffffffffu, mx, off));
    if ((tid & 31) == 0) red[tid >> 5] = mx;
    __syncthreads();
    if (tid == 0) {
        float m = red[0];
#pragma unroll
        for (int i = 1; i < 8; i++) m = fmaxf(m, red[i]);
        s_bmax = m;
        g_keep[slice] = (m >= DW_THR) ? 1 : 0;
    }
    __syncthreads();

    if (s_bmax >= DW_THR && tid < 224) {
        float* yo = g_y + (size_t)slice * 3136 + band * 7 * 56 + 2 * p;
#pragma unroll
        for (int j = 0; j < 7; j++)
            *(float2*)(yo + j * 56) = lv[j];
    }
}

// ---------------------------------------------------------------------------
// Per-batch compaction of kept channels
// ---------------------------------------------------------------------------
__global__ void compact_kernel() {
    const int b = blockIdx.x;
    const int tid = threadIdx.x;              // 128 threads
    __shared__ int wcnt[4];
    const int f = g_keep[b * 128 + tid];
    const unsigned bal = __ballot_sync(0xffffffffu, f);
    const int lane = tid & 31, w = tid >> 5;
    const int pre = __popc(bal & ((1u << lane) - 1u));
    if (lane == 0) wcnt[w] = __popc(bal);
    __syncthreads();
    int off = 0;
#pragma unroll
    for (int i = 0; i < 4; i++) if (i < w) off += wcnt[i];
    if (f) g_idx[b * 128 + off + pre] = tid;
    if (tid == 0) g_cnt[b] = wcnt[0] + wcnt[1] + wcnt[2] + wcnt[3];
}

// ---------------------------------------------------------------------------
// Pointwise conv + BN2 + ReLU + BLOCK-LOCAL prune.
// Block = 64 O x 3136 HW stripe. grid (4 o-tiles, 64 b) = 256 blocks.
// W staged ONCE (all cnt4 rows, sW[128][66] = 33.8KB). Y staged per
// (hw-chunk, k-subtile of 32) in sY[32][68] = 8.7KB. Total ~43KB smem.
// Thread (tx16, ty16): 4 o's x 4 hw per chunk; acc persists across k-subtiles.
// Per-o max in registers; failing rows zeroed by the owning block at the end.
// ---------------------------------------------------------------------------
#define KSUB 32
__global__ __launch_bounds__(256) void pw_kernel(
    const float* __restrict__ pw_w, const float* __restrict__ pw_b,
    const float* __restrict__ g2,  const float* __restrict__ b2,
    const float* __restrict__ m2,  const float* __restrict__ v2,
    float* __restrict__ out)
{
    __shared__ float sW[128][66];            // [k][o] 64 used + 2 pad
    __shared__ float sY[KSUB][68];           // [k][hw] 64 used + 4 pad
    __shared__ int   sidx[128];
    __shared__ unsigned char sfail[64];

    const int tid = threadIdx.x;
    const int tx = tid & 15;                 // hw: 16 x 4 floats
    const int ty = tid >> 4;                 // o : 16 x 4 o's
    const int ob = blockIdx.x * 64;
    const int b  = blockIdx.y;

    const int cnt  = g_cnt[b];
    const int cnt4 = (cnt + 3) & ~3;         // pad to 4; padded rows zero
    const int nsub = (cnt4 + KSUB - 1) / KSUB;

    if (tid < 128) sidx[tid] = (tid < cnt) ? g_idx[b * 128 + tid] : -1;
    __syncthreads();

    // stage W once: sW[k][oo] for k < cnt4 (zeros for padded k)
    for (int i = tid; i < cnt4 * 64; i += 256) {
        int k = i >> 6, oo = i & 63;
        int ch = sidx[k];
        sW[k][oo] = (ch >= 0) ? pw_w[(ob + oo) * 128 + ch] : 0.f;
    }
    // (ordered before first compute by the sync inside the chunk loop)

    // BN constants for this thread's 4 o's
    float sc[4], tc[4], m[4];
    float* orow[4];
#pragma unroll
    for (int r = 0; r < 4; r++) {
        int o = ob + ty * 4 + r;
        sc[r] = g2[o] * rsqrtf(v2[o] + EPSV);
        tc[r] = fmaf(pw_b[o] - m2[o], sc[r], b2[o]);
        m[r] = 0.f;
        orow[r] = out + ((size_t)(b * 256 + o)) * 3136;
    }

    for (int it = 0; it < 49; it++) {
        const int hw = it * 64;

        unsigned long long acc[2][4];        // [o-pair][hw]
#pragma unroll
        for (int p = 0; p < 2; p++)
#pragma unroll
            for (int q = 0; q < 4; q++) acc[p][q] = 0ull;

        for (int kt = 0; kt < nsub; kt++) {
            const int kbase = kt * KSUB;
            int klim = cnt4 - kbase;
            if (klim > KSUB) klim = KSUB;

            // stage Y subtile: klim x 16 float4
            for (int i = tid; i < klim * 16; i += 256) {
                int lk = i >> 4, f4 = i & 15;
                int ch = sidx[kbase + lk];
                float4 v = make_float4(0.f, 0.f, 0.f, 0.f);
                if (ch >= 0)
                    v = *(const float4*)(g_y + ((size_t)(b * 128 + ch)) * 3136 + hw + f4 * 4);
                *(float4*)&sY[lk][f4 * 4] = v;
            }
            __syncthreads();   // Y subtile (and W on first pass) ready

            for (int lk0 = 0; lk0 < klim; lk0 += 4) {
#pragma unroll
                for (int ku = 0; ku < 4; ku++) {
                    int lk = lk0 + ku;
                    int gk = kbase + lk;
                    float4 Y = *(const float4*)&sY[lk][tx * 4];
                    unsigned long long w01 = *(const unsigned long long*)&sW[gk][ty * 4];
                    unsigned long long w23 = *(const unsigned long long*)&sW[gk][ty * 4 + 2];
                    unsigned long long yx = pk2(Y.x, Y.x), yy = pk2(Y.y, Y.y);
                    unsigned long long yz = pk2(Y.z, Y.z), yw = pk2(Y.w, Y.w);
                    acc[0][0] = fma2(w01, yx, acc[0][0]);
                    acc[0][1] = fma2(w01, yy, acc[0][1]);
                    acc[0][2] = fma2(w01, yz, acc[0][2]);
                    acc[0][3] = fma2(w01, yw, acc[0][3]);
                    acc[1][0] = fma2(w23, yx, acc[1][0]);
                    acc[1][1] = fma2(w23, yy, acc[1][1]);
                    acc[1][2] = fma2(w23, yz, acc[1][2]);
                    acc[1][3] = fma2(w23, yw, acc[1][3]);
                }
            }
            __syncthreads();   // protect sY restage
        }

        // epilogue: BN2 + ReLU + max + store
        float z[4][4];
#pragma unroll
        for (int q = 0; q < 4; q++) {
            float2 a01 = upk2(acc[0][q]);
            float2 a23 = upk2(acc[1][q]);
            z[0][q] = fmaxf(fmaf(a01.x, sc[0], tc[0]), 0.f);
            z[1][q] = fmaxf(fmaf(a01.y, sc[1], tc[1]), 0.f);
            z[2][q] = fmaxf(fmaf(a23.x, sc[2], tc[2]), 0.f);
            z[3][q] = fmaxf(fmaf(a23.y, sc[3], tc[3]), 0.f);
        }
#pragma unroll
        for (int r = 0; r < 4; r++) {
            m[r] = fmaxf(m[r], fmaxf(fmaxf(z[r][0], z[r][1]),
                                     fmaxf(z[r][2], z[r][3])));
            *(float4*)(orow[r] + hw + tx * 4) =
                make_float4(z[r][0], z[r][1], z[r][2], z[r][3]);
        }
    }

    // per-o max over the 16 tx lanes (xor<16 stays within same ty group)
#pragma unroll
    for (int r = 0; r < 4; r++) {
#pragma unroll
        for (int off = 1; off < 16; off <<= 1)
            m[r] = fmaxf(m[r], __shfl_xor_sync(0xffffffffu, m[r], off));
    }
    if (tx == 0) {
#pragma unroll
        for (int r = 0; r < 4; r++)
            sfail[ty * 4 + r] = (m[r] < PW_THR) ? 1 : 0;
    }
    __syncthreads();

    // block-local prune: zero failing rows (rare; uniform branch)
    const float4 zz = make_float4(0.f, 0.f, 0.f, 0.f);
    for (int oo = 0; oo < 64; oo++) {
        if (sfail[oo]) {
            float4* p4 = (float4*)(out + ((size_t)(b * 256 + ob + oo)) * 3136);
            for (int i = tid; i < 784; i += 256) p4[i] = zz;
        }
    }
}

// ---------------------------------------------------------------------------
extern "C" void kernel_launch(void* const* d_in, const int* in_sizes, int n_in,
                              void* d_out, int out_size)
{
    const float* x    = (const float*)d_in[0];
    const float* dw_w = (const float*)d_in[1];
    const float* dw_b = (const float*)d_in[2];
    const float* g1   = (const float*)d_in[3];
    const float* b1   = (const float*)d_in[4];
    const float* m1   = (const float*)d_in[5];
    const float* v1   = (const float*)d_in[6];
    const float* pw_w = (const float*)d_in[7];
    const float* pw_b = (const float*)d_in[8];
    const float* g2   = (const float*)d_in[9];
    const float* b2   = (const float*)d_in[10];
    const float* m2   = (const float*)d_in[11];
    const float* v2   = (const float*)d_in[12];
    float* out = (float*)d_out;

    dw_kernel<<<64 * 128, 256>>>(x, dw_w, dw_b, g1, b1, m1, v1);
    compact_kernel<<<64, 128>>>();
    pw_kernel<<<dim3(4, 64), 256>>>(pw_w, pw_b, g2, b2, m2, v2, out);
}

// round 11
// speedup vs baseline: 1.2828x; 1.0506x over previous
#include <cuda_runtime.h>

#define EPSV   1e-5f
#define DW_THR 4.0f
#define PW_THR 0.001f

// Shapes: B=64, C=128, O=256, H=W=56, HW=3136
__device__ float g_y[64 * 128 * 3136];   // pruned depthwise output [B,C,HW]
__device__ int   g_keep[64 * 128];       // per-(b,c) keep flag
__device__ int   g_idx[64 * 128];        // per-b compacted kept-channel list
__device__ int   g_cnt[64];              // per-b kept count

// ---------------------------------------------------------------------------
// packed fp32x2 helpers (Blackwell FFMA2)
// ---------------------------------------------------------------------------
__device__ __forceinline__ unsigned long long fma2(unsigned long long a,
                                                   unsigned long long b,
                                                   unsigned long long c) {
    unsigned long long d;
    asm("fma.rn.f32x2 %0, %1, %2, %3;" : "=l"(d) : "l"(a), "l"(b), "l"(c));
    return d;
}
__device__ __forceinline__ unsigned long long mul2(unsigned long long a,
                                                   unsigned long long b) {
    unsigned long long d;
    asm("mul.rn.f32x2 %0, %1, %2;" : "=l"(d) : "l"(a), "l"(b));
    return d;
}
__device__ __forceinline__ unsigned long long pk2(float lo, float hi) {
    unsigned long long d;
    asm("mov.b64 %0, {%1, %2};" : "=l"(d) : "f"(lo), "f"(hi));
    return d;
}
__device__ __forceinline__ float2 upk2(unsigned long long v) {
    float2 r;
    asm("mov.b64 {%0, %1}, %2;" : "=f"(r.x), "=f"(r.y) : "l"(v));
    return r;
}

// ---------------------------------------------------------------------------
// Depthwise 3x3 + bias + BN1 + ReLU + per-(b,c) prune. (passing, 38.5us)
// ---------------------------------------------------------------------------
__global__ __launch_bounds__(256) void dw_kernel(
    const float* __restrict__ x,
    const float* __restrict__ dw_w, const float* __restrict__ dw_b,
    const float* __restrict__ g1,  const float* __restrict__ b1,
    const float* __restrict__ m1,  const float* __restrict__ v1)
{
    __shared__ float sx[3136];
    __shared__ float red[8];
    __shared__ float s_bmax;

    const int slice = blockIdx.x;          // b*128 + c
    const int c = slice & 127;
    const float* xs = x + (size_t)slice * 3136;

    const unsigned long long ww0 = pk2(dw_w[c*9+0], dw_w[c*9+0]);
    const unsigned long long ww1 = pk2(dw_w[c*9+1], dw_w[c*9+1]);
    const unsigned long long ww2 = pk2(dw_w[c*9+2], dw_w[c*9+2]);
    const unsigned long long ww3 = pk2(dw_w[c*9+3], dw_w[c*9+3]);
    const unsigned long long ww4 = pk2(dw_w[c*9+4], dw_w[c*9+4]);
    const unsigned long long ww5 = pk2(dw_w[c*9+5], dw_w[c*9+5]);
    const unsigned long long ww6 = pk2(dw_w[c*9+6], dw_w[c*9+6]);
    const unsigned long long ww7 = pk2(dw_w[c*9+7], dw_w[c*9+7]);
    const unsigned long long ww8 = pk2(dw_w[c*9+8], dw_w[c*9+8]);
    const float s = g1[c] * rsqrtf(v1[c] + EPSV);
    const float t = fmaf(dw_b[c] - m1[c], s, b1[c]);
    const unsigned long long ss = pk2(s, s);
    const unsigned long long tt = pk2(t, t);

    const int tid = threadIdx.x;

    {   // stage slice: 784 coalesced float4
        const float4* x4 = (const float4*)xs;
        float4* s4 = (float4*)sx;
        for (int i = tid; i < 784; i += 256) s4[i] = x4[i];
    }
    __syncthreads();

    float2 lv[7];
    float mx = 0.f;
    int p = 0, band = 0;
    if (tid < 224) {
        band = tid / 28;               // 0..7
        p    = tid - band * 28;        // col pair -> cols 2p, 2p+1
        const bool cL = (p > 0), cR = (p < 27);
        const int col = 2 * p;
        const int r0  = band * 7;

        unsigned long long r0q0, r0q1, r0q2, r1q0, r1q1, r1q2;
        {
            float c0 = 0.f, c1 = 0.f, c2 = 0.f, c3 = 0.f;
            if (r0 > 0) {
                int a = (r0 - 1) * 56 + col;
                c0 = cL ? sx[a - 1] : 0.f;
                c1 = sx[a]; c2 = sx[a + 1];
                c3 = cR ? sx[a + 2] : 0.f;
            }
            r0q0 = pk2(c0, c1); r0q1 = pk2(c1, c2); r0q2 = pk2(c2, c3);
        }
        {
            int a = r0 * 56 + col;
            float c0 = cL ? sx[a - 1] : 0.f;
            float c1 = sx[a], c2 = sx[a + 1];
            float c3 = cR ? sx[a + 2] : 0.f;
            r1q0 = pk2(c0, c1); r1q1 = pk2(c1, c2); r1q2 = pk2(c2, c3);
        }

#pragma unroll
        for (int j = 0; j < 7; j++) {
            const int rr = r0 + j + 1;
            unsigned long long r2q0, r2q1, r2q2;
            {
                float c0 = 0.f, c1 = 0.f, c2 = 0.f, c3 = 0.f;
                if (rr < 56) {
                    int a = rr * 56 + col;
                    c0 = cL ? sx[a - 1] : 0.f;
                    c1 = sx[a]; c2 = sx[a + 1];
                    c3 = cR ? sx[a + 2] : 0.f;
                }
                r2q0 = pk2(c0, c1); r2q1 = pk2(c1, c2); r2q2 = pk2(c2, c3);
            }
            unsigned long long acc = mul2(r0q0, ww0);
            acc = fma2(r0q1, ww1, acc); acc = fma2(r0q2, ww2, acc);
            acc = fma2(r1q0, ww3, acc); acc = fma2(r1q1, ww4, acc);
            acc = fma2(r1q2, ww5, acc);
            acc = fma2(r2q0, ww6, acc); acc = fma2(r2q1, ww7, acc);
            acc = fma2(r2q2, ww8, acc);
            acc = fma2(acc, ss, tt);
            float2 pr = upk2(acc);
            float z0 = fmaxf(pr.x, 0.f), z1 = fmaxf(pr.y, 0.f);
            lv[j] = make_float2(z0, z1);
            mx = fmaxf(mx, fmaxf(z0, z1));
            r0q0 = r1q0; r0q1 = r1q1; r0q2 = r1q2;
            r1q0 = r2q0; r1q1 = r2q1; r1q2 = r2q2;
        }
    }

    for (int off = 16; off; off >>= 1)
        mx = fmaxf(mx, __shfl_xor_sync(0xffffffffu, mx, off));
    if ((tid & 31) == 0) red[tid >> 5] = mx;
    __syncthreads();
    if (tid == 0) {
        float m = red[0];
#pragma unroll
        for (int i = 1; i < 8; i++) m = fmaxf(m, red[i]);
        s_bmax = m;
        g_keep[slice] = (m >= DW_THR) ? 1 : 0;
    }
    __syncthreads();

    if (s_bmax >= DW_THR && tid < 224) {
        float* yo = g_y + (size_t)slice * 3136 + band * 7 * 56 + 2 * p;
#pragma unroll
        for (int j = 0; j < 7; j++)
            *(float2*)(yo + j * 56) = lv[j];
    }
}

// ---------------------------------------------------------------------------
// Per-batch compaction of kept channels
// ---------------------------------------------------------------------------
__global__ void compact_kernel() {
    const int b = blockIdx.x;
    const int tid = threadIdx.x;              // 128 threads
    __shared__ int wcnt[4];
    const int f = g_keep[b * 128 + tid];
    const unsigned bal = __ballot_sync(0xffffffffu, f);
    const int lane = tid & 31, w = tid >> 5;
    const int pre = __popc(bal & ((1u << lane) - 1u));
    if (lane == 0) wcnt[w] = __popc(bal);
    __syncthreads();
    int off = 0;
#pragma unroll
    for (int i = 0; i < 4; i++) if (i < w) off += wcnt[i];
    if (f) g_idx[b * 128 + off + pre] = tid;
    if (tid == 0) g_cnt[b] = wcnt[0] + wcnt[1] + wcnt[2] + wcnt[3];
}

// ---------------------------------------------------------------------------
// Pointwise conv + BN2 + ReLU + BLOCK-LOCAL prune.
// Block = 64 O x 3136 HW stripe. grid (4 o-tiles, 64 b) = 256 blocks,
// 512 threads (tx=lane 0..31 -> 128-hw chunks; ty=warp 0..15 -> 4 o's).
// Both W and Y k-subtiled at 32 (~26KB smem). 24 full chunks + one 64 tail.
// Per-o max in registers across full hw; failing rows zeroed locally.
// ---------------------------------------------------------------------------
#define KSUB 32
__global__ __launch_bounds__(512) void pw_kernel(
    const float* __restrict__ pw_w, const float* __restrict__ pw_b,
    const float* __restrict__ g2,  const float* __restrict__ b2,
    const float* __restrict__ m2,  const float* __restrict__ v2,
    float* __restrict__ out)
{
    __shared__ float sWs[KSUB][66];          // [k][o]  64 used + 2 pad
    __shared__ float sYs[KSUB][132];         // [k][hw] 128 used + 4 pad
    __shared__ int   sidx[128];
    __shared__ unsigned char sfail[64];

    const int tid = threadIdx.x;
    const int tx = tid & 31;                 // hw: 32 lanes x 4 floats
    const int ty = tid >> 5;                 // o : 16 warps x 4 o's
    const int ob = blockIdx.x * 64;
    const int b  = blockIdx.y;

    const int cnt  = g_cnt[b];
    const int cnt4 = (cnt + 3) & ~3;         // pad to 4; padded rows zero
    const int nsub = (cnt4 + KSUB - 1) / KSUB;

    if (tid < 128) sidx[tid] = (tid < cnt) ? g_idx[b * 128 + tid] : -1;
    __syncthreads();

    // BN constants for this thread's 4 o's
    float sc[4], tc[4], m[4];
    float* orow[4];
#pragma unroll
    for (int r = 0; r < 4; r++) {
        int o = ob + ty * 4 + r;
        sc[r] = g2[o] * rsqrtf(v2[o] + EPSV);
        tc[r] = fmaf(pw_b[o] - m2[o], sc[r], b2[o]);
        m[r] = 0.f;
        orow[r] = out + ((size_t)(b * 256 + o)) * 3136;
    }

    for (int it = 0; it < 25; it++) {
        const int hw0 = it * 128;
        const bool full = (it < 24);                 // tail chunk is 64 wide
        const bool live = full | (tx < 16);          // lanes with real hw

        unsigned long long acc[2][4];                // [o-pair][hw]
#pragma unroll
        for (int p = 0; p < 2; p++)
#pragma unroll
            for (int q = 0; q < 4; q++) acc[p][q] = 0ull;

        for (int kt = 0; kt < nsub; kt++) {
            const int kbase = kt * KSUB;
            int klim = cnt4 - kbase;
            if (klim > KSUB) klim = KSUB;

            // stage W subtile: klim x 64
            for (int i = tid; i < klim * 64; i += 512) {
                int lk = i >> 6, oo = i & 63;
                int ch = sidx[kbase + lk];
                sWs[lk][oo] = (ch >= 0) ? pw_w[(ob + oo) * 128 + ch] : 0.f;
            }
            // stage Y subtile: klim x 32 f4 (full) or klim x 16 f4 (tail)
            if (full) {
                for (int i = tid; i < klim * 32; i += 512) {
                    int lk = i >> 5, f4 = i & 31;
                    int ch = sidx[kbase + lk];
                    float4 v = make_float4(0.f, 0.f, 0.f, 0.f);
                    if (ch >= 0)
                        v = *(const float4*)(g_y + ((size_t)(b * 128 + ch)) * 3136 + hw0 + f4 * 4);
                    *(float4*)&sYs[lk][f4 * 4] = v;
                }
            } else {
                for (int i = tid; i < klim * 16; i += 512) {
                    int lk = i >> 4, f4 = i & 15;
                    int ch = sidx[kbase + lk];
                    float4 v = make_float4(0.f, 0.f, 0.f, 0.f);
                    if (ch >= 0)
                        v = *(const float4*)(g_y + ((size_t)(b * 128 + ch)) * 3136 + hw0 + f4 * 4);
                    *(float4*)&sYs[lk][f4 * 4] = v;
                }
            }
            __syncthreads();   // subtile ready

            if (live) {
                for (int lk0 = 0; lk0 < klim; lk0 += 4) {
#pragma unroll
                    for (int ku = 0; ku < 4; ku++) {
                        int lk = lk0 + ku;
                        float4 Y = *(const float4*)&sYs[lk][tx * 4];
                        unsigned long long w01 = *(const unsigned long long*)&sWs[lk][ty * 4];
                        unsigned long long w23 = *(const unsigned long long*)&sWs[lk][ty * 4 + 2];
                        unsigned long long yx = pk2(Y.x, Y.x), yy = pk2(Y.y, Y.y);
                        unsigned long long yz = pk2(Y.z, Y.z), yw = pk2(Y.w, Y.w);
                        acc[0][0] = fma2(w01, yx, acc[0][0]);
                        acc[0][1] = fma2(w01, yy, acc[0][1]);
                        acc[0][2] = fma2(w01, yz, acc[0][2]);
                        acc[0][3] = fma2(w01, yw, acc[0][3]);
                        acc[1][0] = fma2(w23, yx, acc[1][0]);
                        acc[1][1] = fma2(w23, yy, acc[1][1]);
                        acc[1][2] = fma2(w23, yz, acc[1][2]);
                        acc[1][3] = fma2(w23, yw, acc[1][3]);
                    }
                }
            }
            __syncthreads();   // protect subtile restage
        }

        // epilogue: BN2 + ReLU + max + store (live lanes only)
        if (live) {
            float z[4][4];
#pragma unroll
            for (int q = 0; q < 4; q++) {
                float2 a01 = upk2(acc[0][q]);
                float2 a23 = upk2(acc[1][q]);
                z[0][q] = fmaxf(fmaf(a01.x, sc[0], tc[0]), 0.f);
                z[1][q] = fmaxf(fmaf(a01.y, sc[1], tc[1]), 0.f);
                z[2][q] = fmaxf(fmaf(a23.x, sc[2], tc[2]), 0.f);
                z[3][q] = fmaxf(fmaf(a23.y, sc[3], tc[3]), 0.f);
            }
#pragma unroll
            for (int r = 0; r < 4; r++) {
                m[r] = fmaxf(m[r], fmaxf(fmaxf(z[r][0], z[r][1]),
                                         fmaxf(z[r][2], z[r][3])));
                *(float4*)(orow[r] + hw0 + tx * 4) =
                    make_float4(z[r][0], z[r][1], z[r][2], z[r][3]);
            }
        }
    }

    // per-o max over 32 lanes (tx == lane)
#pragma unroll
    for (int r = 0; r < 4; r++) {
#pragma unroll
        for (int off = 1; off < 32; off <<= 1)
            m[r] = fmaxf(m[r], __shfl_xor_sync(0xffffffffu, m[r], off));
    }
    if (tx == 0) {
#pragma unroll
        for (int r = 0; r < 4; r++)
            sfail[ty * 4 + r] = (m[r] < PW_THR) ? 1 : 0;
    }
    __syncthreads();

    // block-local prune: zero failing rows (uniform branch per block)
    const float4 zz = make_float4(0.f, 0.f, 0.f, 0.f);
    for (int oo = 0; oo < 64; oo++) {
        if (sfail[oo]) {
            float4* p4 = (float4*)(out + ((size_t)(b * 256 + ob + oo)) * 3136);
            for (int i = tid; i < 784; i += 512) p4[i] = zz;
        }
    }
}

// ---------------------------------------------------------------------------
extern "C" void kernel_launch(void* const* d_in, const int* in_sizes, int n_in,
                              void* d_out, int out_size)
{
    const float* x    = (const float*)d_in[0];
    const float* dw_w = (const float*)d_in[1];
    const float* dw_b = (const float*)d_in[2];
    const float* g1   = (const float*)d_in[3];
    const float* b1   = (const float*)d_in[4];
    const float* m1   = (const float*)d_in[5];
    const float* v1   = (const float*)d_in[6];
    const float* pw_w = (const float*)d_in[7];
    const float* pw_b = (const float*)d_in[8];
    const float* g2   = (const float*)d_in[9];
    const float* b2   = (const float*)d_in[10];
    const float* m2   = (const float*)d_in[11];
    const float* v2   = (const float*)d_in[12];
    float* out = (float*)d_out;

    dw_kernel<<<64 * 128, 256>>>(x, dw_w, dw_b, g1, b1, m1, v1);
    compact_kernel<<<64, 128>>>();
    pw_kernel<<<dim3(4, 64), 512>>>(pw_w, pw_b, g2, b2, m2, v2, out);
}

// round 12
// speedup vs baseline: 1.4050x; 1.0953x over previous
#include <cuda_runtime.h>

#define EPSV   1e-5f
#define DW_THR 4.0f
#define PW_THR 0.001f

// Shapes: B=64, C=128, O=256, H=W=56, HW=3136
__device__ float g_y[64 * 128 * 3136];   // pruned depthwise output [B,C,HW]
__device__ int   g_keep[64 * 128];       // per-(b,c) keep flag
__device__ int   g_idx[64 * 128];        // per-b compacted kept-channel list
__device__ int   g_cnt[64];              // per-b kept count

// ---------------------------------------------------------------------------
// packed fp32x2 helpers (Blackwell FFMA2)
// ---------------------------------------------------------------------------
__device__ __forceinline__ unsigned long long fma2(unsigned long long a,
                                                   unsigned long long b,
                                                   unsigned long long c) {
    unsigned long long d;
    asm("fma.rn.f32x2 %0, %1, %2, %3;" : "=l"(d) : "l"(a), "l"(b), "l"(c));
    return d;
}
__device__ __forceinline__ unsigned long long mul2(unsigned long long a,
                                                   unsigned long long b) {
    unsigned long long d;
    asm("mul.rn.f32x2 %0, %1, %2;" : "=l"(d) : "l"(a), "l"(b));
    return d;
}
__device__ __forceinline__ unsigned long long pk2(float lo, float hi) {
    unsigned long long d;
    asm("mov.b64 %0, {%1, %2};" : "=l"(d) : "f"(lo), "f"(hi));
    return d;
}
__device__ __forceinline__ float2 upk2(unsigned long long v) {
    float2 r;
    asm("mov.b64 {%0, %1}, %2;" : "=f"(r.x), "=f"(r.y) : "l"(v));
    return r;
}

// ---------------------------------------------------------------------------
// Depthwise 3x3 + bias + BN1 + ReLU + per-(b,c) prune. (passing, 38.5us)
// ---------------------------------------------------------------------------
__global__ __launch_bounds__(256) void dw_kernel(
    const float* __restrict__ x,
    const float* __restrict__ dw_w, const float* __restrict__ dw_b,
    const float* __restrict__ g1,  const float* __restrict__ b1,
    const float* __restrict__ m1,  const float* __restrict__ v1)
{
    __shared__ float sx[3136];
    __shared__ float red[8];
    __shared__ float s_bmax;

    const int slice = blockIdx.x;          // b*128 + c
    const int c = slice & 127;
    const float* xs = x + (size_t)slice * 3136;

    const unsigned long long ww0 = pk2(dw_w[c*9+0], dw_w[c*9+0]);
    const unsigned long long ww1 = pk2(dw_w[c*9+1], dw_w[c*9+1]);
    const unsigned long long ww2 = pk2(dw_w[c*9+2], dw_w[c*9+2]);
    const unsigned long long ww3 = pk2(dw_w[c*9+3], dw_w[c*9+3]);
    const unsigned long long ww4 = pk2(dw_w[c*9+4], dw_w[c*9+4]);
    const unsigned long long ww5 = pk2(dw_w[c*9+5], dw_w[c*9+5]);
    const unsigned long long ww6 = pk2(dw_w[c*9+6], dw_w[c*9+6]);
    const unsigned long long ww7 = pk2(dw_w[c*9+7], dw_w[c*9+7]);
    const unsigned long long ww8 = pk2(dw_w[c*9+8], dw_w[c*9+8]);
    const float s = g1[c] * rsqrtf(v1[c] + EPSV);
    const float t = fmaf(dw_b[c] - m1[c], s, b1[c]);
    const unsigned long long ss = pk2(s, s);
    const unsigned long long tt = pk2(t, t);

    const int tid = threadIdx.x;

    {   // stage slice: 784 coalesced float4
        const float4* x4 = (const float4*)xs;
        float4* s4 = (float4*)sx;
        for (int i = tid; i < 784; i += 256) s4[i] = x4[i];
    }
    __syncthreads();

    float2 lv[7];
    float mx = 0.f;
    int p = 0, band = 0;
    if (tid < 224) {
        band = tid / 28;               // 0..7
        p    = tid - band * 28;        // col pair -> cols 2p, 2p+1
        const bool cL = (p > 0), cR = (p < 27);
        const int col = 2 * p;
        const int r0  = band * 7;

        unsigned long long r0q0, r0q1, r0q2, r1q0, r1q1, r1q2;
        {
            float c0 = 0.f, c1 = 0.f, c2 = 0.f, c3 = 0.f;
            if (r0 > 0) {
                int a = (r0 - 1) * 56 + col;
                c0 = cL ? sx[a - 1] : 0.f;
                c1 = sx[a]; c2 = sx[a + 1];
                c3 = cR ? sx[a + 2] : 0.f;
            }
            r0q0 = pk2(c0, c1); r0q1 = pk2(c1, c2); r0q2 = pk2(c2, c3);
        }
        {
            int a = r0 * 56 + col;
            float c0 = cL ? sx[a - 1] : 0.f;
            float c1 = sx[a], c2 = sx[a + 1];
            float c3 = cR ? sx[a + 2] : 0.f;
            r1q0 = pk2(c0, c1); r1q1 = pk2(c1, c2); r1q2 = pk2(c2, c3);
        }

#pragma unroll
        for (int j = 0; j < 7; j++) {
            const int rr = r0 + j + 1;
            unsigned long long r2q0, r2q1, r2q2;
            {
                float c0 = 0.f, c1 = 0.f, c2 = 0.f, c3 = 0.f;
                if (rr < 56) {
                    int a = rr * 56 + col;
                    c0 = cL ? sx[a - 1] : 0.f;
                    c1 = sx[a]; c2 = sx[a + 1];
                    c3 = cR ? sx[a + 2] : 0.f;
                }
                r2q0 = pk2(c0, c1); r2q1 = pk2(c1, c2); r2q2 = pk2(c2, c3);
            }
            unsigned long long acc = mul2(r0q0, ww0);
            acc = fma2(r0q1, ww1, acc); acc = fma2(r0q2, ww2, acc);
            acc = fma2(r1q0, ww3, acc); acc = fma2(r1q1, ww4, acc);
            acc = fma2(r1q2, ww5, acc);
            acc = fma2(r2q0, ww6, acc); acc = fma2(r2q1, ww7, acc);
            acc = fma2(r2q2, ww8, acc);
            acc = fma2(acc, ss, tt);
            float2 pr = upk2(acc);
            float z0 = fmaxf(pr.x, 0.f), z1 = fmaxf(pr.y, 0.f);
            lv[j] = make_float2(z0, z1);
            mx = fmaxf(mx, fmaxf(z0, z1));
            r0q0 = r1q0; r0q1 = r1q1; r0q2 = r1q2;
            r1q0 = r2q0; r1q1 = r2q1; r1q2 = r2q2;
        }
    }

    for (int off = 16; off; off >>= 1)
        mx = fmaxf(mx, __shfl_xor_sync(0xffffffffu, mx, off));
    if ((tid & 31) == 0) red[tid >> 5] = mx;
    __syncthreads();
    if (tid == 0) {
        float m = red[0];
#pragma unroll
        for (int i = 1; i < 8; i++) m = fmaxf(m, red[i]);
        s_bmax = m;
        g_keep[slice] = (m >= DW_THR) ? 1 : 0;
    }
    __syncthreads();

    if (s_bmax >= DW_THR && tid < 224) {
        float* yo = g_y + (size_t)slice * 3136 + band * 7 * 56 + 2 * p;
#pragma unroll
        for (int j = 0; j < 7; j++)
            *(float2*)(yo + j * 56) = lv[j];
    }
}

// ---------------------------------------------------------------------------
// Per-batch compaction of kept channels
// ---------------------------------------------------------------------------
__global__ void compact_kernel() {
    const int b = blockIdx.x;
    const int tid = threadIdx.x;              // 128 threads
    __shared__ int wcnt[4];
    const int f = g_keep[b * 128 + tid];
    const unsigned bal = __ballot_sync(0xffffffffu, f);
    const int lane = tid & 31, w = tid >> 5;
    const int pre = __popc(bal & ((1u << lane) - 1u));
    if (lane == 0) wcnt[w] = __popc(bal);
    __syncthreads();
    int off = 0;
#pragma unroll
    for (int i = 0; i < 4; i++) if (i < w) off += wcnt[i];
    if (f) g_idx[b * 128 + off + pre] = tid;
    if (tid == 0) g_cnt[b] = wcnt[0] + wcnt[1] + wcnt[2] + wcnt[3];
}

// ---------------------------------------------------------------------------
// Pointwise conv + BN2 + ReLU + BLOCK-LOCAL prune.
// Block = 32 O x 3136 HW stripe. grid (8 o-tiles, 64 b) = 512 blocks,
// 256 threads (tx=lane -> 128-hw chunks; ty=warp 0..7 -> 4 o's each).
// W/Y k-subtiled at 32 (~21.5KB smem). 24 full chunks + one 64 tail.
// Per-o max in registers across full hw; failing rows zeroed locally.
// ---------------------------------------------------------------------------
#define KSUB 32
__global__ __launch_bounds__(256, 4) void pw_kernel(
    const float* __restrict__ pw_w, const float* __restrict__ pw_b,
    const float* __restrict__ g2,  const float* __restrict__ b2,
    const float* __restrict__ m2,  const float* __restrict__ v2,
    float* __restrict__ out)
{
    __shared__ float sWs[KSUB][36];          // [k][o]  32 used + 4 pad (144B ✓)
    __shared__ float sYs[KSUB][132];         // [k][hw] 128 used + 4 pad (528B ✓)
    __shared__ int   sidx[128];
    __shared__ unsigned char sfail[32];

    const int tid = threadIdx.x;
    const int tx = tid & 31;                 // hw: 32 lanes x 4 floats
    const int ty = tid >> 5;                 // o : 8 warps x 4 o's
    const int ob = blockIdx.x * 32;
    const int b  = blockIdx.y;

    const int cnt  = g_cnt[b];
    const int cnt4 = (cnt + 3) & ~3;         // pad to 4; padded rows zero
    const int nsub = (cnt4 + KSUB - 1) / KSUB;

    if (tid < 128) sidx[tid] = (tid < cnt) ? g_idx[b * 128 + tid] : -1;
    __syncthreads();

    // BN constants for this thread's 4 o's
    float sc[4], tc[4], m[4];
    float* orow[4];
#pragma unroll
    for (int r = 0; r < 4; r++) {
        int o = ob + ty * 4 + r;
        sc[r] = g2[o] * rsqrtf(v2[o] + EPSV);
        tc[r] = fmaf(pw_b[o] - m2[o], sc[r], b2[o]);
        m[r] = 0.f;
        orow[r] = out + ((size_t)(b * 256 + o)) * 3136;
    }

    for (int it = 0; it < 25; it++) {
        const int hw0 = it * 128;
        const bool full = (it < 24);                 // tail chunk is 64 wide
        const bool live = full | (tx < 16);          // lanes with real hw

        unsigned long long acc[2][4];                // [o-pair][hw]
#pragma unroll
        for (int p = 0; p < 2; p++)
#pragma unroll
            for (int q = 0; q < 4; q++) acc[p][q] = 0ull;

        for (int kt = 0; kt < nsub; kt++) {
            const int kbase = kt * KSUB;
            int klim = cnt4 - kbase;
            if (klim > KSUB) klim = KSUB;

            // stage W subtile: klim x 32 (one element per thread per pass)
            for (int i = tid; i < klim * 32; i += 256) {
                int lk = i >> 5, oo = i & 31;
                int ch = sidx[kbase + lk];
                sWs[lk][oo] = (ch >= 0) ? pw_w[(ob + oo) * 128 + ch] : 0.f;
            }
            // stage Y subtile: klim x 32 f4 (full) or klim x 16 f4 (tail)
            if (full) {
                for (int i = tid; i < klim * 32; i += 256) {
                    int lk = i >> 5, f4 = i & 31;
                    int ch = sidx[kbase + lk];
                    float4 v = make_float4(0.f, 0.f, 0.f, 0.f);
                    if (ch >= 0)
                        v = *(const float4*)(g_y + ((size_t)(b * 128 + ch)) * 3136 + hw0 + f4 * 4);
                    *(float4*)&sYs[lk][f4 * 4] = v;
                }
            } else {
                for (int i = tid; i < klim * 16; i += 256) {
                    int lk = i >> 4, f4 = i & 15;
                    int ch = sidx[kbase + lk];
                    float4 v = make_float4(0.f, 0.f, 0.f, 0.f);
                    if (ch >= 0)
                        v = *(const float4*)(g_y + ((size_t)(b * 128 + ch)) * 3136 + hw0 + f4 * 4);
                    *(float4*)&sYs[lk][f4 * 4] = v;
                }
            }
            __syncthreads();   // subtile ready

            if (live) {
                for (int lk0 = 0; lk0 < klim; lk0 += 4) {
#pragma unroll
                    for (int ku = 0; ku < 4; ku++) {
                        int lk = lk0 + ku;
                        float4 Y = *(const float4*)&sYs[lk][tx * 4];
                        unsigned long long w01 = *(const unsigned long long*)&sWs[lk][ty * 4];
                        unsigned long long w23 = *(const unsigned long long*)&sWs[lk][ty * 4 + 2];
                        unsigned long long yx = pk2(Y.x, Y.x), yy = pk2(Y.y, Y.y);
                        unsigned long long yz = pk2(Y.z, Y.z), yw = pk2(Y.w, Y.w);
                        acc[0][0] = fma2(w01, yx, acc[0][0]);
                        acc[0][1] = fma2(w01, yy, acc[0][1]);
                        acc[0][2] = fma2(w01, yz, acc[0][2]);
                        acc[0][3] = fma2(w01, yw, acc[0][3]);
                        acc[1][0] = fma2(w23, yx, acc[1][0]);
                        acc[1][1] = fma2(w23, yy, acc[1][1]);
                        acc[1][2] = fma2(w23, yz, acc[1][2]);
                        acc[1][3] = fma2(w23, yw, acc[1][3]);
                    }
                }
            }
            __syncthreads();   // protect subtile restage
        }

        // epilogue: BN2 + ReLU + max + store (live lanes only)
        if (live) {
            float z[4][4];
#pragma unroll
            for (int q = 0; q < 4; q++) {
                float2 a01 = upk2(acc[0][q]);
                float2 a23 = upk2(acc[1][q]);
                z[0][q] = fmaxf(fmaf(a01.x, sc[0], tc[0]), 0.f);
                z[1][q] = fmaxf(fmaf(a01.y, sc[1], tc[1]), 0.f);
                z[2][q] = fmaxf(fmaf(a23.x, sc[2], tc[2]), 0.f);
                z[3][q] = fmaxf(fmaf(a23.y, sc[3], tc[3]), 0.f);
            }
#pragma unroll
            for (int r = 0; r < 4; r++) {
                m[r] = fmaxf(m[r], fmaxf(fmaxf(z[r][0], z[r][1]),
                                         fmaxf(z[r][2], z[r][3])));
                *(float4*)(orow[r] + hw0 + tx * 4) =
                    make_float4(z[r][0], z[r][1], z[r][2], z[r][3]);
            }
        }
    }

    // per-o max over 32 lanes (tx == lane)
#pragma unroll
    for (int r = 0; r < 4; r++) {
#pragma unroll
        for (int off = 1; off < 32; off <<= 1)
            m[r] = fmaxf(m[r], __shfl_xor_sync(0xffffffffu, m[r], off));
    }
    if (tx == 0) {
#pragma unroll
        for (int r = 0; r < 4; r++)
            sfail[ty * 4 + r] = (m[r] < PW_THR) ? 1 : 0;
    }
    __syncthreads();

    // block-local prune: zero failing rows (uniform branch per block)
    const float4 zz = make_float4(0.f, 0.f, 0.f, 0.f);
    for (int oo = 0; oo < 32; oo++) {
        if (sfail[oo]) {
            float4* p4 = (float4*)(out + ((size_t)(b * 256 + ob + oo)) * 3136);
            for (int i = tid; i < 784; i += 256) p4[i] = zz;
        }
    }
}

// ---------------------------------------------------------------------------
extern "C" void kernel_launch(void* const* d_in, const int* in_sizes, int n_in,
                              void* d_out, int out_size)
{
    const float* x    = (const float*)d_in[0];
    const float* dw_w = (const float*)d_in[1];
    const float* dw_b = (const float*)d_in[2];
    const float* g1   = (const float*)d_in[3];
    const float* b1   = (const float*)d_in[4];
    const float* m1   = (const float*)d_in[5];
    const float* v1   = (const float*)d_in[6];
    const float* pw_w = (const float*)d_in[7];
    const float* pw_b = (const float*)d_in[8];
    const float* g2   = (const float*)d_in[9];
    const float* b2   = (const float*)d_in[10];
    const float* m2   = (const float*)d_in[11];
    const float* v2   = (const float*)d_in[12];
    float* out = (float*)d_out;

    dw_kernel<<<64 * 128, 256>>>(x, dw_w, dw_b, g1, b1, m1, v1);
    compact_kernel<<<64, 128>>>();
    pw_kernel<<<dim3(8, 64), 256>>>(pw_w, pw_b, g2, b2, m2, v2, out);
}